// round 16
// baseline (speedup 1.0000x reference)
#include <cuda_runtime.h>
#include <cuda_fp16.h>
#include <mma.h>
#include <stdint.h>

using namespace nvcuda;

#define N_NODES 100000
#define N_EDGES 1600000
#define F_IN  64
#define F_HID 64
#define F_OUT 32

#define SCAN_B 98      // 98 * 1024 >= N_NODES; single wave on 148 SMs
#define GEMM1_B 782    // (N_NODES + 127) / 128
#define FILL_B 6250    // (N_EDGES + 255) / 256

// ---------------- static device scratch ----------------
__device__ float  g_dinv[N_NODES];
__device__ __half g_xh  [N_NODES * F_IN];    // x converted to fp16 (unscaled)
__device__ __half g_xws [N_NODES * F_HID];   // (x@W1)*dinv, fp16
__device__ __half g_h16 [N_NODES * F_HID];   // relu hidden, fp16
__device__ __half g_hws [N_NODES * F_OUT];   // (h@W2)*dinv, fp16
__device__ int    g_cnt [N_NODES];           // BSS-zero; re-zeroed each call
__device__ int    g_off [N_NODES + 1];
__device__ int    g_cur [N_NODES];
__device__ int    g_csr [N_EDGES];
__device__ int    g_scanval [SCAN_B];
__device__ int    g_scanflag[SCAN_B];
__device__ int    g_done;

// dtype detection: int64 layout (values<2^31) => odd words zero
__device__ __forceinline__ int detect64_t0(const int* __restrict__ w) {
    int nz = 0;
#pragma unroll
    for (int j = 1; j < 16; j += 2) nz |= w[j];
    return nz == 0;
}

// ---------------- histogram over dst + fused x->fp16 conversion ----------------
__global__ void k_hist(const int* __restrict__ ew, const float* __restrict__ x) {
    __shared__ int s64;
    if (threadIdx.x == 0) s64 = detect64_t0(ew);
    __syncthreads();
    int e = blockIdx.x * blockDim.x + threadIdx.x;

    if (e < N_NODES * F_IN / 4) {
        float4 v = __ldg((const float4*)x + e);
        __half2 h0 = __floats2half2_rn(v.x, v.y);
        __half2 h1 = __floats2half2_rn(v.z, v.w);
        uint2 u;
        u.x = *(unsigned int*)&h0;
        u.y = *(unsigned int*)&h1;
        ((uint2*)g_xh)[e] = u;
    }

    if (e >= N_EDGES) return;
    int d = s64 ? ew[2 * N_EDGES + 2 * e] : ew[N_EDGES + e];
    atomicAdd(&g_cnt[d], 1);
}

// ---------------- single-pass scan ----------------
__global__ void __launch_bounds__(1024) k_scan1() {
    int b = blockIdx.x, t = threadIdx.x;
    int i = b * 1024 + t;
    int lane = t & 31, wid = t >> 5;
    int c = (i < N_NODES) ? g_cnt[i] : 0;

    int inc = c;
#pragma unroll
    for (int o = 1; o < 32; o <<= 1) {
        int u = __shfl_up_sync(0xffffffffu, inc, o);
        if (lane >= o) inc += u;
    }
    __shared__ int wpre[32];
    __shared__ int s_base;
    if (lane == 31) wpre[wid] = inc;
    __syncthreads();

    if (wid == 0) {
        int s = wpre[lane];
        int sinc = s;
#pragma unroll
        for (int o = 1; o < 32; o <<= 1) {
            int u = __shfl_up_sync(0xffffffffu, sinc, o);
            if (lane >= o) sinc += u;
        }
        wpre[lane] = sinc - s;
        if (lane == 31) {
            g_scanval[b] = sinc;
            __threadfence();
            atomicExch(&g_scanflag[b], 1);
        }
    } else if (wid == 1) {
        int base = 0;
        for (int j = lane; j < b; j += 32) {
            while (atomicAdd(&g_scanflag[j], 0) == 0) {}
            __threadfence();
            base += *((volatile int*)(g_scanval + j));
        }
#pragma unroll
        for (int o = 16; o > 0; o >>= 1)
            base += __shfl_down_sync(0xffffffffu, base, o);
        if (lane == 0) s_base = base;
    }
    __syncthreads();

    if (i < N_NODES) {
        int exc = inc - c + wpre[wid] + s_base;
        g_off[i] = exc;
        g_cur[i] = exc;
        g_dinv[i] = rsqrtf((float)c + 1.0f);
        g_cnt[i] = 0;
    }
    if (b == 0 && t == 0) g_off[N_NODES] = N_EDGES;

    __syncthreads();
    if (t == 0) {
        __threadfence();
        int d = atomicAdd(&g_done, 1);
        if (d == gridDim.x - 1) {
            for (int j = 0; j < SCAN_B; j++) g_scanflag[j] = 0;
            g_done = 0;
            __threadfence();
        }
    }
}

// ---------------- fused: gemm1 (blocks [0,GEMM1_B)) + fill (rest) ----------------
#define LDX1 72   // padded half ldm for A tile
#define LDW1 72   // padded half ldm for W1
#define LDO1 68   // padded float ldm for epilogue
__global__ void __launch_bounds__(256) k_fillgemm1(const int* __restrict__ ew,
                                                   const float* __restrict__ W) {
    __shared__ __half wh[F_IN * LDW1];                 // 9216 B
    __shared__ float obuf[128 * LDO1];                 // 34816 B (aliases xh)
    int tid = threadIdx.x;

    if (blockIdx.x >= GEMM1_B) {
        // ---- fill CSR path ----
        __shared__ int s64;
        if (tid == 0) s64 = detect64_t0(ew);
        __syncthreads();
        int e = (blockIdx.x - GEMM1_B) * 256 + tid;
        if (e >= N_EDGES) return;
        int s, d;
        if (s64) {
            s = ew[2 * e];
            d = ew[2 * N_EDGES + 2 * e];
        } else {
            s = ew[e];
            d = ew[N_EDGES + e];
        }
        int slot = atomicAdd(&g_cur[d], 1);
        g_csr[slot] = s;
        return;
    }

    // ---- gemm1 path: xws = fp16((x @ W1) * dinv) ----
    __half* xh = (__half*)obuf;                        // 128*LDX1 halves = 18432 B
    int rowb = min((int)blockIdx.x * 128, N_NODES - 128);

    for (int i = tid; i < F_IN * (F_HID / 2); i += 256) {
        int r = i >> 5, cp = i & 31;
        float2 w2 = *(const float2*)(W + r * F_HID + cp * 2);
        *(__half2*)(wh + r * LDW1 + cp * 2) = __floats2half2_rn(w2.x, w2.y);
    }
    for (int i = tid; i < 128 * 8; i += 256) {
        int r = i >> 3, c = i & 7;
        uint4 v = *(const uint4*)(g_xh + (size_t)(rowb + r) * F_IN + c * 8);
        *(uint4*)(xh + r * LDX1 + c * 8) = v;
    }
    __syncthreads();

    int warp = tid >> 5, lane = tid & 31;

    wmma::fragment<wmma::accumulator, 16, 16, 16, float> acc[4];
#pragma unroll
    for (int n = 0; n < 4; n++) wmma::fill_fragment(acc[n], 0.0f);

#pragma unroll
    for (int k = 0; k < 4; k++) {
        wmma::fragment<wmma::matrix_a, 16, 16, 16, __half, wmma::row_major> a;
        wmma::load_matrix_sync(a, xh + (warp * 16) * LDX1 + k * 16, LDX1);
#pragma unroll
        for (int n = 0; n < 4; n++) {
            wmma::fragment<wmma::matrix_b, 16, 16, 16, __half, wmma::row_major> bf;
            wmma::load_matrix_sync(bf, wh + (k * 16) * LDW1 + n * 16, LDW1);
            wmma::mma_sync(acc[n], a, bf, acc[n]);
        }
    }
    __syncthreads();   // xh reads complete before obuf overwrite

    float* my = obuf + warp * 16 * LDO1;
#pragma unroll
    for (int n = 0; n < 4; n++)
        wmma::store_matrix_sync(my + n * 16, acc[n], LDO1, wmma::mem_row_major);
    __syncwarp();

#pragma unroll
    for (int r = 0; r < 16; r++) {
        int row = rowb + warp * 16 + r;
        float s = g_dinv[row];
        float lo = my[r * LDO1 + lane * 2]     * s;
        float hi = my[r * LDO1 + lane * 2 + 1] * s;
        *(__half2*)(g_xws + (size_t)row * F_HID + lane * 2) = __floats2half2_rn(lo, hi);
    }
}

// ---------------- aggregate layer 1 + hidden epilogue (warp per node) ----------
__global__ void __launch_bounds__(256) k_agg1(const float* __restrict__ b1) {
    int node = (blockIdx.x * 256 + threadIdx.x) >> 5;
    int lane = threadIdx.x & 31;
    if (node >= N_NODES) return;

    int k   = g_off[node];
    int end = g_off[node + 1];
    int col = lane * 2;

    float2 acc0 = make_float2(0.f, 0.f);
    float2 acc1 = make_float2(0.f, 0.f);

    for (; k + 8 <= end; k += 8) {
        int idx[8];
#pragma unroll
        for (int j = 0; j < 8; j++) idx[j] = __ldg(g_csr + k + j);
        __half2 v[8];
#pragma unroll
        for (int j = 0; j < 8; j++)
            v[j] = *(const __half2*)(g_xws + (size_t)idx[j] * F_HID + col);
#pragma unroll
        for (int j = 0; j < 8; j += 2) {
            float2 f0 = __half22float2(v[j]);
            float2 f1 = __half22float2(v[j + 1]);
            acc0.x += f0.x; acc0.y += f0.y;
            acc1.x += f1.x; acc1.y += f1.y;
        }
    }
    for (; k < end; k++) {
        int s = __ldg(g_csr + k);
        float2 f = __half22float2(*(const __half2*)(g_xws + (size_t)s * F_HID + col));
        acc0.x += f.x; acc0.y += f.y;
    }

    float2 self = __half22float2(*(const __half2*)(g_xws + (size_t)node * F_HID + col));
    float sc = g_dinv[node];
    float2 b = ((const float2*)b1)[lane];
    float rx = fmaxf(sc * (acc0.x + acc1.x + self.x) + b.x, 0.f);
    float ry = fmaxf(sc * (acc0.y + acc1.y + self.y) + b.y, 0.f);
    *(__half2*)(g_h16 + (size_t)node * F_HID + col) = __floats2half2_rn(rx, ry);
}

// ---------------- GEMM2 (wmma fp16): hws = fp16((h @ W2) * dinv) ----------------
#define LDX2 72   // padded half ldm for A tile
#define LDW2 40   // padded half ldm for W2
#define LDO2 36   // padded float ldm for epilogue
__global__ void __launch_bounds__(256) k_gemm2(const float* __restrict__ W) {
    __shared__ __half wh[F_HID * LDW2];                // 5120 B
    __shared__ float obuf[128 * LDO2];                 // 18432 B (aliases hh)
    __half* hh = (__half*)obuf;                        // 128*LDX2 halves = 18432 B

    int tid = threadIdx.x;
    int rowb = min((int)blockIdx.x * 128, N_NODES - 128);

    for (int i = tid; i < F_HID * (F_OUT / 2); i += 256) {
        int r = i >> 4, cp = i & 15;
        float2 w2 = *(const float2*)(W + r * F_OUT + cp * 2);
        *(__half2*)(wh + r * LDW2 + cp * 2) = __floats2half2_rn(w2.x, w2.y);
    }
    for (int i = tid; i < 128 * 8; i += 256) {
        int r = i >> 3, c = i & 7;
        uint4 v = *(const uint4*)(g_h16 + (size_t)(rowb + r) * F_HID + c * 8);
        *(uint4*)(hh + r * LDX2 + c * 8) = v;
    }
    __syncthreads();

    int warp = tid >> 5, lane = tid & 31;

    wmma::fragment<wmma::accumulator, 16, 16, 16, float> acc[2];
#pragma unroll
    for (int n = 0; n < 2; n++) wmma::fill_fragment(acc[n], 0.0f);

#pragma unroll
    for (int k = 0; k < 4; k++) {
        wmma::fragment<wmma::matrix_a, 16, 16, 16, __half, wmma::row_major> a;
        wmma::load_matrix_sync(a, hh + (warp * 16) * LDX2 + k * 16, LDX2);
#pragma unroll
        for (int n = 0; n < 2; n++) {
            wmma::fragment<wmma::matrix_b, 16, 16, 16, __half, wmma::row_major> bf;
            wmma::load_matrix_sync(bf, wh + (k * 16) * LDW2 + n * 16, LDW2);
            wmma::mma_sync(acc[n], a, bf, acc[n]);
        }
    }
    __syncthreads();

    float* my = obuf + warp * 16 * LDO2;
#pragma unroll
    for (int n = 0; n < 2; n++)
        wmma::store_matrix_sync(my + n * 16, acc[n], LDO2, wmma::mem_row_major);
    __syncwarp();

#pragma unroll
    for (int i = 0; i < 8; i++) {
        int e = lane + i * 32;
        int r = e >> 4;
        int c = e & 15;
        int row = rowb + warp * 16 + r;
        float s = g_dinv[row];
        float lo = my[r * LDO2 + c * 2]     * s;
        float hi = my[r * LDO2 + c * 2 + 1] * s;
        *(__half2*)(g_hws + (size_t)row * F_OUT + c * 2) = __floats2half2_rn(lo, hi);
    }
}

// ---------------- aggregate layer 2 + output epilogue (warp per node) ----------
__global__ void __launch_bounds__(256) k_agg2(const float* __restrict__ b2,
                                              float* __restrict__ out) {
    int node = (blockIdx.x * 256 + threadIdx.x) >> 5;
    int lane = threadIdx.x & 31;
    if (node >= N_NODES) return;

    int k   = g_off[node];
    int end = g_off[node + 1];

    float acc0 = 0.f, acc1 = 0.f;

    for (; k + 8 <= end; k += 8) {
        int idx[8];
#pragma unroll
        for (int j = 0; j < 8; j++) idx[j] = __ldg(g_csr + k + j);
        float v[8];
#pragma unroll
        for (int j = 0; j < 8; j++)
            v[j] = __half2float(g_hws[(size_t)idx[j] * F_OUT + lane]);
        acc0 += (v[0] + v[2]) + (v[4] + v[6]);
        acc1 += (v[1] + v[3]) + (v[5] + v[7]);
    }
    for (; k < end; k++) {
        int s = __ldg(g_csr + k);
        acc0 += __half2float(g_hws[(size_t)s * F_OUT + lane]);
    }

    float self = __half2float(g_hws[(size_t)node * F_OUT + lane]);
    float sc = g_dinv[node];
    out[(size_t)node * F_OUT + lane] = sc * (acc0 + acc1 + self) + b2[lane];
}

// ---------------- launch ----------------
extern "C" void kernel_launch(void* const* d_in, const int* in_sizes, int n_in,
                              void* d_out, int out_size) {
    const float* x  = (const float*)d_in[0];
    const int*   ew = (const int*)d_in[1];
    const float* W1 = (const float*)d_in[2];
    const float* b1 = (const float*)d_in[3];
    const float* W2 = (const float*)d_in[4];
    const float* b2 = (const float*)d_in[5];
    float* out = (float*)d_out;

    const int T = 256;

    k_hist<<<(N_EDGES + T - 1) / T, T>>>(ew, x);
    k_scan1<<<SCAN_B, 1024>>>();
    k_fillgemm1<<<GEMM1_B + FILL_B, T>>>(ew, W1);
    k_agg1<<<(N_NODES * 32 + T - 1) / T, T>>>(b1);

    k_gemm2<<<(N_NODES + 127) / 128, T>>>(W2);
    k_agg2<<<(N_NODES * 32 + T - 1) / T, T>>>(b2, out);
}

// round 17
// speedup vs baseline: 1.0641x; 1.0641x over previous
#include <cuda_runtime.h>
#include <cuda_fp16.h>
#include <mma.h>
#include <stdint.h>

using namespace nvcuda;

#define N_NODES 100000
#define N_EDGES 1600000
#define F_IN  64
#define F_HID 64
#define F_OUT 32

#define SCAN_B 98   // 98 * 1024 >= N_NODES; single wave on 148 SMs

// ---------------- static device scratch ----------------
__device__ float  g_dinv[N_NODES];
__device__ __half g_xh  [N_NODES * F_IN];    // x converted to fp16 (unscaled)
__device__ __half g_xws [N_NODES * F_HID];   // (x@W1)*dinv, fp16
__device__ __half g_h16 [N_NODES * F_HID];   // relu hidden, fp16
__device__ __half g_hws [N_NODES * F_OUT];   // (h@W2)*dinv, fp16
__device__ int    g_cnt [N_NODES];           // BSS-zero; re-zeroed each call
__device__ int    g_off [N_NODES + 1];
__device__ int    g_cur [N_NODES];
__device__ int    g_csr [N_EDGES];
__device__ int    g_scanval [SCAN_B];
__device__ int    g_scanflag[SCAN_B];
__device__ int    g_done;

// dtype detection: int64 layout (values<2^31) => odd words zero
__device__ __forceinline__ int detect64_t0(const int* __restrict__ w) {
    int nz = 0;
#pragma unroll
    for (int j = 1; j < 16; j += 2) nz |= w[j];
    return nz == 0;
}

// ---------------- histogram over dst + fused x->fp16 conversion ----------------
__global__ void k_hist(const int* __restrict__ ew, const float* __restrict__ x) {
    __shared__ int s64;
    if (threadIdx.x == 0) s64 = detect64_t0(ew);
    __syncthreads();
    int e = blockIdx.x * blockDim.x + threadIdx.x;

    if (e < N_NODES * F_IN / 4) {
        float4 v = __ldg((const float4*)x + e);
        __half2 h0 = __floats2half2_rn(v.x, v.y);
        __half2 h1 = __floats2half2_rn(v.z, v.w);
        uint2 u;
        u.x = *(unsigned int*)&h0;
        u.y = *(unsigned int*)&h1;
        ((uint2*)g_xh)[e] = u;
    }

    if (e >= N_EDGES) return;
    int d = s64 ? ew[2 * N_EDGES + 2 * e] : ew[N_EDGES + e];
    atomicAdd(&g_cnt[d], 1);
}

// ---------------- single-pass scan ----------------
__global__ void __launch_bounds__(1024) k_scan1() {
    int b = blockIdx.x, t = threadIdx.x;
    int i = b * 1024 + t;
    int lane = t & 31, wid = t >> 5;
    int c = (i < N_NODES) ? g_cnt[i] : 0;

    int inc = c;
#pragma unroll
    for (int o = 1; o < 32; o <<= 1) {
        int u = __shfl_up_sync(0xffffffffu, inc, o);
        if (lane >= o) inc += u;
    }
    __shared__ int wpre[32];
    __shared__ int s_base;
    if (lane == 31) wpre[wid] = inc;
    __syncthreads();

    if (wid == 0) {
        int s = wpre[lane];
        int sinc = s;
#pragma unroll
        for (int o = 1; o < 32; o <<= 1) {
            int u = __shfl_up_sync(0xffffffffu, sinc, o);
            if (lane >= o) sinc += u;
        }
        wpre[lane] = sinc - s;
        if (lane == 31) {
            g_scanval[b] = sinc;
            __threadfence();
            atomicExch(&g_scanflag[b], 1);
        }
    } else if (wid == 1) {
        int base = 0;
        for (int j = lane; j < b; j += 32) {
            while (atomicAdd(&g_scanflag[j], 0) == 0) {}
            __threadfence();
            base += *((volatile int*)(g_scanval + j));
        }
#pragma unroll
        for (int o = 16; o > 0; o >>= 1)
            base += __shfl_down_sync(0xffffffffu, base, o);
        if (lane == 0) s_base = base;
    }
    __syncthreads();

    if (i < N_NODES) {
        int exc = inc - c + wpre[wid] + s_base;
        g_off[i] = exc;
        g_cur[i] = exc;
        g_dinv[i] = rsqrtf((float)c + 1.0f);
        g_cnt[i] = 0;
    }
    if (b == 0 && t == 0) g_off[N_NODES] = N_EDGES;

    __syncthreads();
    if (t == 0) {
        __threadfence();
        int d = atomicAdd(&g_done, 1);
        if (d == gridDim.x - 1) {
            for (int j = 0; j < SCAN_B; j++) g_scanflag[j] = 0;
            g_done = 0;
            __threadfence();
        }
    }
}

// ---------------- fill CSR ----------------
__global__ void k_fill(const int* __restrict__ ew) {
    __shared__ int s64;
    if (threadIdx.x == 0) s64 = detect64_t0(ew);
    __syncthreads();
    int e = blockIdx.x * blockDim.x + threadIdx.x;
    if (e >= N_EDGES) return;
    int s, d;
    if (s64) {
        s = ew[2 * e];
        d = ew[2 * N_EDGES + 2 * e];
    } else {
        s = ew[e];
        d = ew[N_EDGES + e];
    }
    int slot = atomicAdd(&g_cur[d], 1);
    g_csr[slot] = s;
}

// ---------------- GEMM1 (wmma fp16): xws = fp16((x @ W1) * dinv) ----------------
#define LDX1 72
#define LDW1 72
#define LDO1 68
__global__ void __launch_bounds__(256) k_gemm1(const float* __restrict__ W) {
    __shared__ __half wh[F_IN * LDW1];                 // 9216 B
    __shared__ float obuf[128 * LDO1];                 // 34816 B (aliases xh)
    __half* xh = (__half*)obuf;

    int tid = threadIdx.x;
    int rowb = min((int)blockIdx.x * 128, N_NODES - 128);

    for (int i = tid; i < F_IN * (F_HID / 2); i += 256) {
        int r = i >> 5, cp = i & 31;
        float2 w2 = *(const float2*)(W + r * F_HID + cp * 2);
        *(__half2*)(wh + r * LDW1 + cp * 2) = __floats2half2_rn(w2.x, w2.y);
    }
    for (int i = tid; i < 128 * 8; i += 256) {
        int r = i >> 3, c = i & 7;
        uint4 v = *(const uint4*)(g_xh + (size_t)(rowb + r) * F_IN + c * 8);
        *(uint4*)(xh + r * LDX1 + c * 8) = v;
    }
    __syncthreads();

    int warp = tid >> 5, lane = tid & 31;

    wmma::fragment<wmma::accumulator, 16, 16, 16, float> acc[4];
#pragma unroll
    for (int n = 0; n < 4; n++) wmma::fill_fragment(acc[n], 0.0f);

#pragma unroll
    for (int k = 0; k < 4; k++) {
        wmma::fragment<wmma::matrix_a, 16, 16, 16, __half, wmma::row_major> a;
        wmma::load_matrix_sync(a, xh + (warp * 16) * LDX1 + k * 16, LDX1);
#pragma unroll
        for (int n = 0; n < 4; n++) {
            wmma::fragment<wmma::matrix_b, 16, 16, 16, __half, wmma::row_major> bf;
            wmma::load_matrix_sync(bf, wh + (k * 16) * LDW1 + n * 16, LDW1);
            wmma::mma_sync(acc[n], a, bf, acc[n]);
        }
    }
    __syncthreads();

    float* my = obuf + warp * 16 * LDO1;
#pragma unroll
    for (int n = 0; n < 4; n++)
        wmma::store_matrix_sync(my + n * 16, acc[n], LDO1, wmma::mem_row_major);
    __syncwarp();

#pragma unroll
    for (int r = 0; r < 16; r++) {
        int row = rowb + warp * 16 + r;
        float s = g_dinv[row];
        float lo = my[r * LDO1 + lane * 2]     * s;
        float hi = my[r * LDO1 + lane * 2 + 1] * s;
        *(__half2*)(g_xws + (size_t)row * F_HID + lane * 2) = __floats2half2_rn(lo, hi);
    }
}

// ---------------- aggregate layer 1 + hidden epilogue (warp per node) ----------
// pairwise fp16 adds cut cvt+FADD issue count ~30%
__global__ void __launch_bounds__(256) k_agg1(const float* __restrict__ b1) {
    int node = (blockIdx.x * 256 + threadIdx.x) >> 5;
    int lane = threadIdx.x & 31;
    if (node >= N_NODES) return;

    int k   = g_off[node];
    int end = g_off[node + 1];
    int col = lane * 2;

    float2 acc0 = make_float2(0.f, 0.f);
    float2 acc1 = make_float2(0.f, 0.f);

    for (; k + 8 <= end; k += 8) {
        int idx[8];
#pragma unroll
        for (int j = 0; j < 8; j++) idx[j] = __ldg(g_csr + k + j);
        __half2 v[8];
#pragma unroll
        for (int j = 0; j < 8; j++)
            v[j] = *(const __half2*)(g_xws + (size_t)idx[j] * F_HID + col);
        // pairwise fp16 add, then fp32 accumulate (4 pair-sums)
        __half2 p0 = __hadd2(v[0], v[1]);
        __half2 p1 = __hadd2(v[2], v[3]);
        __half2 p2 = __hadd2(v[4], v[5]);
        __half2 p3 = __hadd2(v[6], v[7]);
        float2 f0 = __half22float2(p0);
        float2 f1 = __half22float2(p1);
        float2 f2 = __half22float2(p2);
        float2 f3 = __half22float2(p3);
        acc0.x += f0.x + f2.x; acc0.y += f0.y + f2.y;
        acc1.x += f1.x + f3.x; acc1.y += f1.y + f3.y;
    }
    for (; k < end; k++) {
        int s = __ldg(g_csr + k);
        float2 f = __half22float2(*(const __half2*)(g_xws + (size_t)s * F_HID + col));
        acc0.x += f.x; acc0.y += f.y;
    }

    float2 self = __half22float2(*(const __half2*)(g_xws + (size_t)node * F_HID + col));
    float sc = g_dinv[node];
    float2 b = ((const float2*)b1)[lane];
    float rx = fmaxf(sc * (acc0.x + acc1.x + self.x) + b.x, 0.f);
    float ry = fmaxf(sc * (acc0.y + acc1.y + self.y) + b.y, 0.f);
    *(__half2*)(g_h16 + (size_t)node * F_HID + col) = __floats2half2_rn(rx, ry);
}

// ---------------- GEMM2 (wmma fp16): hws = fp16((h @ W2) * dinv) ----------------
#define LDX2 72
#define LDW2 40
#define LDO2 36
__global__ void __launch_bounds__(256) k_gemm2(const float* __restrict__ W) {
    __shared__ __half wh[F_HID * LDW2];                // 5120 B
    __shared__ float obuf[128 * LDO2];                 // 18432 B (aliases hh)
    __half* hh = (__half*)obuf;

    int tid = threadIdx.x;
    int rowb = min((int)blockIdx.x * 128, N_NODES - 128);

    for (int i = tid; i < F_HID * (F_OUT / 2); i += 256) {
        int r = i >> 4, cp = i & 15;
        float2 w2 = *(const float2*)(W + r * F_OUT + cp * 2);
        *(__half2*)(wh + r * LDW2 + cp * 2) = __floats2half2_rn(w2.x, w2.y);
    }
    for (int i = tid; i < 128 * 8; i += 256) {
        int r = i >> 3, c = i & 7;
        uint4 v = *(const uint4*)(g_h16 + (size_t)(rowb + r) * F_HID + c * 8);
        *(uint4*)(hh + r * LDX2 + c * 8) = v;
    }
    __syncthreads();

    int warp = tid >> 5, lane = tid & 31;

    wmma::fragment<wmma::accumulator, 16, 16, 16, float> acc[2];
#pragma unroll
    for (int n = 0; n < 2; n++) wmma::fill_fragment(acc[n], 0.0f);

#pragma unroll
    for (int k = 0; k < 4; k++) {
        wmma::fragment<wmma::matrix_a, 16, 16, 16, __half, wmma::row_major> a;
        wmma::load_matrix_sync(a, hh + (warp * 16) * LDX2 + k * 16, LDX2);
#pragma unroll
        for (int n = 0; n < 2; n++) {
            wmma::fragment<wmma::matrix_b, 16, 16, 16, __half, wmma::row_major> bf;
            wmma::load_matrix_sync(bf, wh + (k * 16) * LDW2 + n * 16, LDW2);
            wmma::mma_sync(acc[n], a, bf, acc[n]);
        }
    }
    __syncthreads();

    float* my = obuf + warp * 16 * LDO2;
#pragma unroll
    for (int n = 0; n < 2; n++)
        wmma::store_matrix_sync(my + n * 16, acc[n], LDO2, wmma::mem_row_major);
    __syncwarp();

#pragma unroll
    for (int i = 0; i < 8; i++) {
        int e = lane + i * 32;
        int r = e >> 4;
        int c = e & 15;
        int row = rowb + warp * 16 + r;
        float s = g_dinv[row];
        float lo = my[r * LDO2 + c * 2]     * s;
        float hi = my[r * LDO2 + c * 2 + 1] * s;
        *(__half2*)(g_hws + (size_t)row * F_OUT + c * 2) = __floats2half2_rn(lo, hi);
    }
}

// ---------------- aggregate layer 2 + output epilogue (warp per node) ----------
__global__ void __launch_bounds__(256) k_agg2(const float* __restrict__ b2,
                                              float* __restrict__ out) {
    int node = (blockIdx.x * 256 + threadIdx.x) >> 5;
    int lane = threadIdx.x & 31;
    if (node >= N_NODES) return;

    int k   = g_off[node];
    int end = g_off[node + 1];

    float acc0 = 0.f, acc1 = 0.f;

    for (; k + 8 <= end; k += 8) {
        int idx[8];
#pragma unroll
        for (int j = 0; j < 8; j++) idx[j] = __ldg(g_csr + k + j);
        float v[8];
#pragma unroll
        for (int j = 0; j < 8; j++)
            v[j] = __half2float(g_hws[(size_t)idx[j] * F_OUT + lane]);
        acc0 += (v[0] + v[2]) + (v[4] + v[6]);
        acc1 += (v[1] + v[3]) + (v[5] + v[7]);
    }
    for (; k < end; k++) {
        int s = __ldg(g_csr + k);
        acc0 += __half2float(g_hws[(size_t)s * F_OUT + lane]);
    }

    float self = __half2float(g_hws[(size_t)node * F_OUT + lane]);
    float sc = g_dinv[node];
    out[(size_t)node * F_OUT + lane] = sc * (acc0 + acc1 + self) + b2[lane];
}

// ---------------- launch ----------------
extern "C" void kernel_launch(void* const* d_in, const int* in_sizes, int n_in,
                              void* d_out, int out_size) {
    const float* x  = (const float*)d_in[0];
    const int*   ew = (const int*)d_in[1];
    const float* W1 = (const float*)d_in[2];
    const float* b1 = (const float*)d_in[3];
    const float* W2 = (const float*)d_in[4];
    const float* b2 = (const float*)d_in[5];
    float* out = (float*)d_out;

    const int T = 256;

    k_hist<<<(N_EDGES + T - 1) / T, T>>>(ew, x);
    k_scan1<<<SCAN_B, 1024>>>();
    k_fill<<<(N_EDGES + T - 1) / T, T>>>(ew);

    k_gemm1<<<(N_NODES + 127) / 128, T>>>(W1);
    k_agg1<<<(N_NODES * 32 + T - 1) / T, T>>>(b1);

    k_gemm2<<<(N_NODES + 127) / 128, T>>>(W2);
    k_agg2<<<(N_NODES * 32 + T - 1) / T, T>>>(b2, out);
}